// round 2
// baseline (speedup 1.0000x reference)
#include <cuda_runtime.h>
#include <math.h>

#define NN 50000
#define NE 800000
#define HID 128
#define NG 500

// Scratch (device globals: no allocation allowed)
__device__ float g_h[(size_t)NN * HID];          // node features
__device__ float g_P[(size_t)NN * 512];          // [Fdst|Sdst|Fsrc|Ssrc] per node
__device__ float g_E[(size_t)NE * 256];          // [Ef|Es] per edge (per layer)
__device__ float g_agg[(size_t)NN * HID];        // message aggregation
__device__ float g_pool[NG * HID];
__device__ float g_cnt[NG];

// ---------------------------------------------------------------------------
// init: h = emb[x]; zero agg/pool/cnt
// ---------------------------------------------------------------------------
__global__ void k_init(const int* __restrict__ x, const float* __restrict__ emb) {
    int idx = blockIdx.x * blockDim.x + threadIdx.x;  // over NN*32 (float4 units)
    if (idx < NN * 32) {
        int n = idx >> 5, q = idx & 31;
        ((float4*)g_h)[idx] = ((const float4*)emb)[x[n] * 32 + q];
        ((float4*)g_agg)[idx] = make_float4(0.f, 0.f, 0.f, 0.f);
    }
    if (idx < NG * 32) ((float4*)g_pool)[idx] = make_float4(0.f, 0.f, 0.f, 0.f);
    if (idx < NG) g_cnt[idx] = 0.f;
}

// ---------------------------------------------------------------------------
// Generic small GEMM: out[M, ldo] tiles of 64x64, K in {128,32}.
// Column block (64 cols) cb: kind = cb>>7 selects weight pointer (W0..W3) and
// optional bias (b0 for kind0, b1 for kind1). Weight is row-major [*,128],
// we use cols wcol..wcol+63 of it.
// ---------------------------------------------------------------------------
#define BM 64
#define BN 64
#define BK 16
#define ASTR 68  // padded stride

__global__ void k_gemm(const float* __restrict__ A, int M, int K,
                       const float* __restrict__ W0, const float* __restrict__ W1,
                       const float* __restrict__ W2, const float* __restrict__ W3,
                       const float* __restrict__ b0, const float* __restrict__ b1,
                       float* __restrict__ out, int ldo)
{
    __shared__ float As[BK][ASTR];
    __shared__ float Bs[BK][ASTR];

    int cb = blockIdx.y * BN;
    int kind = cb >> 7;
    const float* W = (kind == 0) ? W0 : (kind == 1) ? W1 : (kind == 2) ? W2 : W3;
    const float* bias = (kind == 0) ? b0 : (kind == 1) ? b1 : nullptr;
    int wcol = cb & 127;
    int row0 = blockIdx.x * BM;
    int tid = threadIdx.x;          // 256 threads
    int tx = tid & 15, ty = tid >> 4;

    float acc[4][4];
#pragma unroll
    for (int i = 0; i < 4; i++)
#pragma unroll
        for (int j = 0; j < 4; j++) acc[i][j] = 0.f;

    for (int k0 = 0; k0 < K; k0 += BK) {
        // load A tile 64x16 (transposed into As[k][m])
        {
            int m = tid >> 2, kq = (tid & 3) * 4;
            float4 v = make_float4(0.f, 0.f, 0.f, 0.f);
            int r = row0 + m;
            if (r < M) v = *(const float4*)(A + (size_t)r * K + k0 + kq);
            As[kq + 0][m] = v.x;
            As[kq + 1][m] = v.y;
            As[kq + 2][m] = v.z;
            As[kq + 3][m] = v.w;
        }
        // load B tile 16x64
        {
            int kk = tid >> 4, cq = (tid & 15) * 4;
            float4 v = *(const float4*)(W + (size_t)(k0 + kk) * 128 + wcol + cq);
            *(float4*)&Bs[kk][cq] = v;
        }
        __syncthreads();
#pragma unroll
        for (int kk = 0; kk < BK; kk++) {
            float4 a4 = *(const float4*)&As[kk][ty * 4];
            float4 b4 = *(const float4*)&Bs[kk][tx * 4];
            float a[4] = {a4.x, a4.y, a4.z, a4.w};
            float b[4] = {b4.x, b4.y, b4.z, b4.w};
#pragma unroll
            for (int i = 0; i < 4; i++)
#pragma unroll
                for (int j = 0; j < 4; j++) acc[i][j] += a[i] * b[j];
        }
        __syncthreads();
    }

    float bj[4] = {0.f, 0.f, 0.f, 0.f};
    if (bias) {
#pragma unroll
        for (int j = 0; j < 4; j++) bj[j] = bias[wcol + tx * 4 + j];
    }
#pragma unroll
    for (int i = 0; i < 4; i++) {
        int r = row0 + ty * 4 + i;
        if (r < M) {
            float4 v = make_float4(acc[i][0] + bj[0], acc[i][1] + bj[1],
                                   acc[i][2] + bj[2], acc[i][3] + bj[3]);
            *(float4*)(out + (size_t)r * ldo + cb + tx * 4) = v;
        }
    }
}

// ---------------------------------------------------------------------------
// Edge kernel: one warp per edge.
// zf = P[dst][0:128] + P[src][256:384] + E[e][0:128]
// zs = P[dst][128:256] + P[src][384:512] + E[e][128:256]
// msg = sigmoid(zf) * softplus(zs); atomic-add into agg[dst]
// ---------------------------------------------------------------------------
__device__ __forceinline__ float sigmoidf_(float x) {
    return 1.f / (1.f + __expf(-x));
}
__device__ __forceinline__ float softplusf_(float x) {
    // logaddexp(x, 0) = max(x,0) + log1p(exp(-|x|))
    return fmaxf(x, 0.f) + log1pf(__expf(-fabsf(x)));
}

__global__ void k_edge(const int* __restrict__ ei) {
    int gid = blockIdx.x * blockDim.x + threadIdx.x;
    int e = gid >> 5, lane = gid & 31;
    if (e >= NE) return;
    int src = ei[e];
    int dst = ei[NE + e];

    const float4* pd = (const float4*)(g_P + (size_t)dst * 512);        // 64 f4: F|S dst
    const float4* ps = (const float4*)(g_P + (size_t)src * 512 + 256);  // 64 f4: F|S src
    const float4* ep = (const float4*)(g_E + (size_t)e * 256);

    float4 f0 = pd[lane], f1 = ps[lane], f2 = ep[lane];
    float4 s0 = pd[lane + 32], s1 = ps[lane + 32], s2 = ep[lane + 32];

    float zf[4] = {f0.x + f1.x + f2.x, f0.y + f1.y + f2.y,
                   f0.z + f1.z + f2.z, f0.w + f1.w + f2.w};
    float zs[4] = {s0.x + s1.x + s2.x, s0.y + s1.y + s2.y,
                   s0.z + s1.z + s2.z, s0.w + s1.w + s2.w};

    float* ag = g_agg + (size_t)dst * HID + lane * 4;
#pragma unroll
    for (int j = 0; j < 4; j++) {
        float m = sigmoidf_(zf[j]) * softplusf_(zs[j]);
        atomicAdd(ag + j, m);
    }
}

// ---------------------------------------------------------------------------
// h = relu(h + agg); agg = 0
// ---------------------------------------------------------------------------
__global__ void k_update() {
    int idx = blockIdx.x * blockDim.x + threadIdx.x;  // NN*32
    if (idx >= NN * 32) return;
    float4 h = ((float4*)g_h)[idx];
    float4 a = ((float4*)g_agg)[idx];
    h.x = fmaxf(h.x + a.x, 0.f);
    h.y = fmaxf(h.y + a.y, 0.f);
    h.z = fmaxf(h.z + a.z, 0.f);
    h.w = fmaxf(h.w + a.w, 0.f);
    ((float4*)g_h)[idx] = h;
    ((float4*)g_agg)[idx] = make_float4(0.f, 0.f, 0.f, 0.f);
}

// ---------------------------------------------------------------------------
// pool: atomic sums per graph + counts
// ---------------------------------------------------------------------------
__global__ void k_pool(const int* __restrict__ batch) {
    int idx = blockIdx.x * blockDim.x + threadIdx.x;  // NN*32
    if (idx >= NN * 32) return;
    int n = idx >> 5, q = idx & 31;
    int g = batch[n];
    float4 v = ((float4*)g_h)[idx];
    float* p = g_pool + (size_t)g * HID + q * 4;
    atomicAdd(p + 0, v.x);
    atomicAdd(p + 1, v.y);
    atomicAdd(p + 2, v.z);
    atomicAdd(p + 3, v.w);
    if (q == 0) atomicAdd(&g_cnt[g], 1.f);
}

// ---------------------------------------------------------------------------
// final: out[g] = (pool[g]/max(cnt,1)) @ Wlin + blin   (block per graph)
// ---------------------------------------------------------------------------
__global__ void k_final(const float* __restrict__ Wlin, const float* __restrict__ blin,
                        float* __restrict__ out) {
    __shared__ float p[HID];
    int g = blockIdx.x, t = threadIdx.x;
    float c = fmaxf(g_cnt[g], 1.f);
    p[t] = g_pool[g * HID + t] / c;
    __syncthreads();
    float acc = blin[t];
#pragma unroll 8
    for (int k = 0; k < HID; k++) acc += p[k] * Wlin[k * HID + t];
    out[g * HID + t] = acc;
}

// ---------------------------------------------------------------------------
extern "C" void kernel_launch(void* const* d_in, const int* in_sizes, int n_in,
                              void* d_out, int out_size) {
    const int*   x    = (const int*)d_in[0];
    const int*   ei   = (const int*)d_in[1];
    const float* ea   = (const float*)d_in[2];
    const int*   batch= (const int*)d_in[3];
    const float* emb  = (const float*)d_in[4];
    const float* Wlin = (const float*)d_in[17];
    const float* blin = (const float*)d_in[18];

    float* out = (float*)d_out;

    float* hP = nullptr;  // resolved via device symbols inside kernels

    // init
    {
        int total = NN * 32;
        k_init<<<(total + 255) / 256, 256>>>(x, emb);
    }

    for (int l = 0; l < 3; l++) {
        const float* Wf = (const float*)d_in[5 + 4 * l];
        const float* bf = (const float*)d_in[6 + 4 * l];
        const float* Ws = (const float*)d_in[7 + 4 * l];
        const float* bs = (const float*)d_in[8 + 4 * l];

        // Node projections: P[n][0:128]=h@Wf[0:128]+bf, [128:256]=h@Ws[0:128]+bs,
        //                   [256:384]=h@Wf[128:256],    [384:512]=h@Ws[128:256]
        {
            float* Pp;  cudaGetSymbolAddress((void**)&Pp, g_P);
            float* hp;  cudaGetSymbolAddress((void**)&hp, g_h);
            dim3 grid((NN + BM - 1) / BM, 512 / BN);
            k_gemm<<<grid, 256>>>(hp, NN, 128,
                                  Wf, Ws, Wf + 128 * 128, Ws + 128 * 128,
                                  bf, bs, Pp, 512);
        }
        // Edge-attr projections: E[e][0:128]=ea@Wf[256:288], [128:256]=ea@Ws[256:288]
        {
            float* Ep;  cudaGetSymbolAddress((void**)&Ep, g_E);
            dim3 grid(NE / BM, 256 / BN);
            k_gemm<<<grid, 256>>>(ea, NE, 32,
                                  Wf + 256 * 128, Ws + 256 * 128, nullptr, nullptr,
                                  nullptr, nullptr, Ep, 256);
        }
        // Edge message + scatter
        {
            long long threads = (long long)NE * 32;
            k_edge<<<(int)((threads + 255) / 256), 256>>>(ei);
        }
        // h = relu(h + agg); agg = 0
        {
            int total = NN * 32;
            k_update<<<(total + 255) / 256, 256>>>();
        }
    }

    // pooling
    {
        int total = NN * 32;
        k_pool<<<(total + 255) / 256, 256>>>(batch);
    }
    // final linear
    k_final<<<NG, HID>>>(Wlin, blin, out);

    (void)hP; (void)in_sizes; (void)n_in; (void)out_size;
}

// round 5
// speedup vs baseline: 1.6830x; 1.6830x over previous
#include <cuda_runtime.h>
#include <cuda_bf16.h>
#include <cstdint>
#include <math.h>

#define NN 50000
#define NE 800000
#define HID 128
#define NG 500

// Scratch (device globals: no allocation allowed)
__device__ float g_h[(size_t)NN * HID];              // node features
__device__ float g_P[(size_t)NN * 512];              // [Fdst|Sdst|Fsrc|Ssrc] per node
__device__ __nv_bfloat16 g_Ebf[(size_t)NE * 256];    // [Ef|Es] per edge (bf16)
__device__ float g_agg[(size_t)NN * HID];            // message aggregation
__device__ float g_pool[NG * HID];
__device__ float g_cnt[NG];

// ---------------------------------------------------------------------------
// init: h = emb[x]; zero agg/pool/cnt
// ---------------------------------------------------------------------------
__global__ void k_init(const int* __restrict__ x, const float* __restrict__ emb) {
    int idx = blockIdx.x * blockDim.x + threadIdx.x;  // over NN*32 (float4 units)
    if (idx < NN * 32) {
        int n = idx >> 5, q = idx & 31;
        ((float4*)g_h)[idx] = ((const float4*)emb)[x[n] * 32 + q];
        ((float4*)g_agg)[idx] = make_float4(0.f, 0.f, 0.f, 0.f);
    }
    if (idx < NG * 32) ((float4*)g_pool)[idx] = make_float4(0.f, 0.f, 0.f, 0.f);
    if (idx < NG) g_cnt[idx] = 0.f;
}

// ---------------------------------------------------------------------------
// Tensor-core GEMM (tf32 mma.sync m16n8k8).
// C[M, ldo], CTA tile 128(M) x 128(N). blockIdx.y = kind selects weight slice
// (all slices are full-width 128 cols) and optional bias. K in {128, 32}.
// ---------------------------------------------------------------------------
__device__ __forceinline__ uint32_t f2tf32(float x) {
    uint32_t u;
    asm("cvt.rna.tf32.f32 %0, %1;" : "=r"(u) : "f"(x));
    return u;
}

__device__ __forceinline__ void mma_tf32(float c[4], const uint32_t a[4],
                                         const uint32_t b[2]) {
    asm volatile(
        "mma.sync.aligned.m16n8k8.row.col.f32.tf32.tf32.f32 "
        "{%0,%1,%2,%3}, {%4,%5,%6,%7}, {%8,%9}, {%0,%1,%2,%3};"
        : "+f"(c[0]), "+f"(c[1]), "+f"(c[2]), "+f"(c[3])
        : "r"(a[0]), "r"(a[1]), "r"(a[2]), "r"(a[3]), "r"(b[0]), "r"(b[1]));
}

__device__ __forceinline__ void store2(float* p, float x, float y) {
    *(float2*)p = make_float2(x, y);
}
__device__ __forceinline__ void store2(__nv_bfloat16* p, float x, float y) {
    *(__nv_bfloat162*)p = __floats2bfloat162_rn(x, y);
}

#define SSTR 136  // smem row stride (uint32): avoids bank conflicts on frag loads

template <typename OT>
__global__ void k_gemm_tc(const float* __restrict__ A, int M, int K,
                          const float* __restrict__ W0, const float* __restrict__ W1,
                          const float* __restrict__ W2, const float* __restrict__ W3,
                          const float* __restrict__ b0, const float* __restrict__ b1,
                          OT* __restrict__ out, int ldo)
{
    __shared__ uint32_t Ast[16][SSTR];  // [k][m] transposed
    __shared__ uint32_t Bs[16][SSTR];   // [k][n]

    int kind = blockIdx.y;
    const float* W = (kind == 0) ? W0 : (kind == 1) ? W1 : (kind == 2) ? W2 : W3;
    const float* bias = (kind == 0) ? b0 : (kind == 1) ? b1 : nullptr;
    int cb = kind * 128;
    int row0 = blockIdx.x * 128;
    int tid = threadIdx.x;           // 256 threads = 8 warps
    int lane = tid & 31, wid = tid >> 5;
    int wm = (wid & 1) * 64, wn = (wid >> 1) * 32;
    int gid4 = lane >> 2, tig = lane & 3;

    float acc[4][4][4];
#pragma unroll
    for (int i = 0; i < 4; i++)
#pragma unroll
        for (int j = 0; j < 4; j++)
#pragma unroll
            for (int r = 0; r < 4; r++) acc[i][j][r] = 0.f;

    for (int k0 = 0; k0 < K; k0 += 16) {
        // Load A tile 128x16 -> Ast[k][m] (transposed, tf32)
#pragma unroll
        for (int i = 0; i < 2; i++) {
            int id = tid * 2 + i;
            int r = id >> 2, q = (id & 3) * 4;
            float4 v = make_float4(0.f, 0.f, 0.f, 0.f);
            int gr = row0 + r;
            if (gr < M) v = *(const float4*)(A + (size_t)gr * K + k0 + q);
            Ast[q + 0][r] = f2tf32(v.x);
            Ast[q + 1][r] = f2tf32(v.y);
            Ast[q + 2][r] = f2tf32(v.z);
            Ast[q + 3][r] = f2tf32(v.w);
        }
        // Load B tile 16x128 -> Bs[k][n] (tf32)
#pragma unroll
        for (int i = 0; i < 2; i++) {
            int id = tid * 2 + i;
            int kk = id >> 5, n4 = (id & 31) * 4;
            float4 v = *(const float4*)(W + (size_t)(k0 + kk) * 128 + n4);
            uint4 u = make_uint4(f2tf32(v.x), f2tf32(v.y), f2tf32(v.z), f2tf32(v.w));
            *(uint4*)&Bs[kk][n4] = u;
        }
        __syncthreads();

#pragma unroll
        for (int kk = 0; kk < 16; kk += 8) {
            uint32_t a[4][4], b[4][2];
#pragma unroll
            for (int i = 0; i < 4; i++) {
                int m0 = wm + i * 16 + gid4;
                a[i][0] = Ast[kk + tig][m0];
                a[i][1] = Ast[kk + tig][m0 + 8];
                a[i][2] = Ast[kk + tig + 4][m0];
                a[i][3] = Ast[kk + tig + 4][m0 + 8];
            }
#pragma unroll
            for (int j = 0; j < 4; j++) {
                int n0 = wn + j * 8 + gid4;
                b[j][0] = Bs[kk + tig][n0];
                b[j][1] = Bs[kk + tig + 4][n0];
            }
#pragma unroll
            for (int i = 0; i < 4; i++)
#pragma unroll
                for (int j = 0; j < 4; j++) mma_tf32(acc[i][j], a[i], b[j]);
        }
        __syncthreads();
    }

    // Epilogue: bias + store (float2 / bf16x2 pairs, coalesced per quad)
#pragma unroll
    for (int j = 0; j < 4; j++) {
        int cl = wn + j * 8 + 2 * tig;   // local col (0..127), even
        float bx = 0.f, by = 0.f;
        if (bias) { bx = bias[cl]; by = bias[cl + 1]; }
#pragma unroll
        for (int i = 0; i < 4; i++) {
            int r0 = row0 + wm + i * 16 + gid4;
            if (r0 < M)
                store2(out + (size_t)r0 * ldo + cb + cl, acc[i][j][0] + bx, acc[i][j][1] + by);
            if (r0 + 8 < M)
                store2(out + (size_t)(r0 + 8) * ldo + cb + cl, acc[i][j][2] + bx, acc[i][j][3] + by);
        }
    }
}

// ---------------------------------------------------------------------------
// Edge kernel: one warp per edge.
// zf = P[dst][0:128] + P[src][256:384] + E[e][0:128]
// zs = P[dst][128:256] + P[src][384:512] + E[e][128:256]
// msg = sigmoid(zf) * softplus(zs); red.v4 into agg[dst]
// ---------------------------------------------------------------------------
__device__ __forceinline__ float sigmoidf_(float x) {
    return 1.f / (1.f + __expf(-x));
}
__device__ __forceinline__ float softplusf_(float x) {
    return fmaxf(x, 0.f) + log1pf(__expf(-fabsf(x)));
}

__global__ void k_edge(const int* __restrict__ ei) {
    int gid = blockIdx.x * blockDim.x + threadIdx.x;
    int e = gid >> 5, lane = gid & 31;
    if (e >= NE) return;
    int src = ei[e];
    int dst = ei[NE + e];

    const float4* pd = (const float4*)(g_P + (size_t)dst * 512);        // F|S dst
    const float4* ps = (const float4*)(g_P + (size_t)src * 512 + 256);  // F|S src
    const uint2* ep = (const uint2*)(g_Ebf + (size_t)e * 256);          // 4 bf16 each

    float4 f0 = pd[lane], f1 = ps[lane];
    float4 s0 = pd[lane + 32], s1 = ps[lane + 32];
    uint2 euf = ep[lane], eus = ep[lane + 32];
    float2 ef0 = __bfloat1622float2(*(__nv_bfloat162*)&euf.x);
    float2 ef1 = __bfloat1622float2(*(__nv_bfloat162*)&euf.y);
    float2 es0 = __bfloat1622float2(*(__nv_bfloat162*)&eus.x);
    float2 es1 = __bfloat1622float2(*(__nv_bfloat162*)&eus.y);

    float zf[4] = {f0.x + f1.x + ef0.x, f0.y + f1.y + ef0.y,
                   f0.z + f1.z + ef1.x, f0.w + f1.w + ef1.y};
    float zs[4] = {s0.x + s1.x + es0.x, s0.y + s1.y + es0.y,
                   s0.z + s1.z + es1.x, s0.w + s1.w + es1.y};

    float m0 = sigmoidf_(zf[0]) * softplusf_(zs[0]);
    float m1 = sigmoidf_(zf[1]) * softplusf_(zs[1]);
    float m2 = sigmoidf_(zf[2]) * softplusf_(zs[2]);
    float m3 = sigmoidf_(zf[3]) * softplusf_(zs[3]);

    float* ag = g_agg + (size_t)dst * HID + lane * 4;
    asm volatile("red.global.add.v4.f32 [%0], {%1,%2,%3,%4};"
                 :: "l"(ag), "f"(m0), "f"(m1), "f"(m2), "f"(m3) : "memory");
}

// ---------------------------------------------------------------------------
// h = relu(h + agg); agg = 0
// ---------------------------------------------------------------------------
__global__ void k_update() {
    int idx = blockIdx.x * blockDim.x + threadIdx.x;  // NN*32
    if (idx >= NN * 32) return;
    float4 h = ((float4*)g_h)[idx];
    float4 a = ((float4*)g_agg)[idx];
    h.x = fmaxf(h.x + a.x, 0.f);
    h.y = fmaxf(h.y + a.y, 0.f);
    h.z = fmaxf(h.z + a.z, 0.f);
    h.w = fmaxf(h.w + a.w, 0.f);
    ((float4*)g_h)[idx] = h;
    ((float4*)g_agg)[idx] = make_float4(0.f, 0.f, 0.f, 0.f);
}

// ---------------------------------------------------------------------------
// pool: atomic sums per graph + counts
// ---------------------------------------------------------------------------
__global__ void k_pool(const int* __restrict__ batch) {
    int idx = blockIdx.x * blockDim.x + threadIdx.x;  // NN*32
    if (idx >= NN * 32) return;
    int n = idx >> 5, q = idx & 31;
    int g = batch[n];
    float4 v = ((float4*)g_h)[idx];
    float* p = g_pool + (size_t)g * HID + q * 4;
    asm volatile("red.global.add.v4.f32 [%0], {%1,%2,%3,%4};"
                 :: "l"(p), "f"(v.x), "f"(v.y), "f"(v.z), "f"(v.w) : "memory");
    if (q == 0) atomicAdd(&g_cnt[g], 1.f);
}

// ---------------------------------------------------------------------------
// final: out[g] = (pool[g]/max(cnt,1)) @ Wlin + blin   (block per graph)
// ---------------------------------------------------------------------------
__global__ void k_final(const float* __restrict__ Wlin, const float* __restrict__ blin,
                        float* __restrict__ out) {
    __shared__ float p[HID];
    int g = blockIdx.x, t = threadIdx.x;
    float c = fmaxf(g_cnt[g], 1.f);
    p[t] = g_pool[g * HID + t] / c;
    __syncthreads();
    float acc = blin[t];
#pragma unroll 8
    for (int k = 0; k < HID; k++) acc += p[k] * Wlin[k * HID + t];
    out[g * HID + t] = acc;
}

// ---------------------------------------------------------------------------
extern "C" void kernel_launch(void* const* d_in, const int* in_sizes, int n_in,
                              void* d_out, int out_size) {
    const int*   x    = (const int*)d_in[0];
    const int*   ei   = (const int*)d_in[1];
    const float* ea   = (const float*)d_in[2];
    const int*   batch= (const int*)d_in[3];
    const float* emb  = (const float*)d_in[4];
    const float* Wlin = (const float*)d_in[17];
    const float* blin = (const float*)d_in[18];

    float* out = (float*)d_out;

    float* Pp;  cudaGetSymbolAddress((void**)&Pp, g_P);
    float* hp;  cudaGetSymbolAddress((void**)&hp, g_h);
    __nv_bfloat16* Ep;  cudaGetSymbolAddress((void**)&Ep, g_Ebf);

    // init
    {
        int total = NN * 32;
        k_init<<<(total + 255) / 256, 256>>>(x, emb);
    }

    for (int l = 0; l < 3; l++) {
        const float* Wf = (const float*)d_in[5 + 4 * l];
        const float* bf = (const float*)d_in[6 + 4 * l];
        const float* Ws = (const float*)d_in[7 + 4 * l];
        const float* bs = (const float*)d_in[8 + 4 * l];

        // Node projections: P[n] = [h@WfA+bf | h@WsA+bs | h@WfB | h@WsB]
        {
            dim3 grid((NN + 127) / 128, 4);
            k_gemm_tc<float><<<grid, 256>>>(hp, NN, 128,
                                            Wf, Ws, Wf + 128 * 128, Ws + 128 * 128,
                                            bf, bs, Pp, 512);
        }
        // Edge-attr projections: E[e] = [ea@Wf[256:288] | ea@Ws[256:288]] (bf16)
        {
            dim3 grid(NE / 128, 2);
            k_gemm_tc<__nv_bfloat16><<<grid, 256>>>(ea, NE, 32,
                                                    Wf + 256 * 128, Ws + 256 * 128,
                                                    nullptr, nullptr,
                                                    nullptr, nullptr, Ep, 256);
        }
        // Edge message + scatter
        {
            long long threads = (long long)NE * 32;
            k_edge<<<(int)((threads + 255) / 256), 256>>>(ei);
        }
        // h = relu(h + agg); agg = 0
        {
            int total = NN * 32;
            k_update<<<(total + 255) / 256, 256>>>();
        }
    }

    // pooling
    {
        int total = NN * 32;
        k_pool<<<(total + 255) / 256, 256>>>(batch);
    }
    // final linear
    k_final<<<NG, HID>>>(Wlin, blin, out);

    (void)in_sizes; (void)n_in; (void)out_size;
}